// round 11
// baseline (speedup 1.0000x reference)
#include <cuda_runtime.h>
#include <cuda_bf16.h>
#include <cstdint>

#define N_NODES 50000
#define D_IN    256
#define D_HID   512
#define N_EDGES 800000
#define KTOT    512           // fused K = D_IN (mean) + D_IN (x)
#define M_PAD   50048         // 391 * 128
#define SCAN_BLOCKS 49        // 49 * 1024 = 50176 >= N_NODES
#define QC      254.0f        // residual radix: a = sA*(q0 + q1/254)

// ---------------- scratch (device globals; allocation-free) ----------------
__device__ int   g_cnt_i[N_NODES];
__device__ int   g_off[N_NODES + 1];
__device__ int   g_cursor[N_NODES];
__device__ int   g_csr[N_EDGES];
__device__ unsigned long long g_pub[SCAN_BLOCKS];
__device__ unsigned char g_Aq0[(size_t)M_PAD * KTOT];
__device__ unsigned char g_Aq1[(size_t)M_PAD * KTOT];
__device__ unsigned char g_Bq0[(size_t)D_HID * KTOT];  // [n][k]
__device__ unsigned char g_Bq1[(size_t)D_HID * KTOT];
__device__ float g_sA[M_PAD];
__device__ float g_sB[D_HID];

// ---------------- helpers ----------------
__device__ __forceinline__ uint32_t smem_u32(const void* p) {
    uint32_t a;
    asm("{ .reg .u64 t; cvta.to.shared.u64 t, %1; cvt.u32.u64 %0, t; }" : "=r"(a) : "l"(p));
    return a;
}
// swizzled offset within a 128-row x 128-byte tile: row r, 16B-chunk j
__device__ __forceinline__ uint32_t sw_off(int r, int j) {
    return (uint32_t)(r * 128 + ((j ^ (r & 7)) << 4));
}
__device__ __forceinline__ void ldmatrix_x4(uint32_t* f, uint32_t addr) {
    asm volatile("ldmatrix.sync.aligned.m8n8.x4.shared.b16 {%0,%1,%2,%3}, [%4];"
        : "=r"(f[0]), "=r"(f[1]), "=r"(f[2]), "=r"(f[3]) : "r"(addr));
}
__device__ __forceinline__ void mma_s8(int* d, const uint32_t* a, uint32_t b0, uint32_t b1) {
    asm volatile("mma.sync.aligned.m16n8k32.row.col.s32.s8.s8.s32 "
        "{%0,%1,%2,%3}, {%4,%5,%6,%7}, {%8,%9}, {%0,%1,%2,%3};"
        : "+r"(d[0]), "+r"(d[1]), "+r"(d[2]), "+r"(d[3])
        : "r"(a[0]), "r"(a[1]), "r"(a[2]), "r"(a[3]), "r"(b0), "r"(b1));
}

// per-warp dtype detection: int64 edge_index has zero hi-words.
__device__ __forceinline__ int detect_is64(const unsigned int* __restrict__ e) {
    int lane = threadIdx.x & 31;
    unsigned w = (lane < 8) ? e[2 * lane + 1] : 0u;
    unsigned m = __ballot_sync(0xffffffffu, w != 0u);
    return (m & 0xFFu) == 0u;
}

// quantize 4 floats -> packed q0 byte-word, residuals out
__device__ __forceinline__ uint32_t pack_q0(const float* v, float invs, float* rs) {
    uint32_t w = 0;
#pragma unroll
    for (int j = 0; j < 4; j++) {
        float t = v[j] * invs;
        float q = rintf(t);
        rs[j] = t - q;
        w |= ((uint32_t)((int)q) & 0xFFu) << (8 * j);
    }
    return w;
}
__device__ __forceinline__ uint32_t pack_q1(const float* rs) {
    uint32_t w = 0;
#pragma unroll
    for (int j = 0; j < 4; j++) {
        int q = (int)rintf(rs[j] * QC);
        w |= ((uint32_t)q & 0xFFu) << (8 * j);
    }
    return w;
}

// ---------------- CSR build ----------------
__global__ void zero_kernel() {
    int i = blockIdx.x * blockDim.x + threadIdx.x;
    if (i < N_NODES) g_cnt_i[i] = 0;
    if (i < SCAN_BLOCKS) g_pub[i] = 0ull;
}

__global__ __launch_bounds__(256) void hist_kernel(const void* __restrict__ eidx) {
    int is64 = detect_is64((const unsigned int*)eidx);
    int e = blockIdx.x * blockDim.x + threadIdx.x;
    if (e >= N_EDGES) return;
    int dst = is64 ? (int)((const long long*)eidx)[N_EDGES + e]
                   : ((const int*)eidx)[N_EDGES + e];
    atomicAdd(&g_cnt_i[dst], 1);
}

// single-pass scan with decoupled aggregate lookback (49 blocks co-resident)
__global__ __launch_bounds__(1024) void scan_kernel() {
    __shared__ int sdata[1024];
    __shared__ int s_prefix;
    const int tid = threadIdx.x, b = blockIdx.x;
    const int i = b * 1024 + tid;
    int v = (i < N_NODES) ? g_cnt_i[i] : 0;
    sdata[tid] = v;
    __syncthreads();
#pragma unroll
    for (int ofs = 1; ofs < 1024; ofs <<= 1) {
        int t = (tid >= ofs) ? sdata[tid - ofs] : 0;
        __syncthreads();
        sdata[tid] += t;
        __syncthreads();
    }
    const int incl = sdata[tid];
    const int agg  = sdata[1023];

    if (tid == 0) {
        s_prefix = 0;
        __threadfence();
        atomicExch(&g_pub[b], ((unsigned long long)(unsigned)agg << 1) | 1ull);
    }
    __syncthreads();
    if (tid < b) {
        unsigned long long p;
        do { p = atomicAdd(&g_pub[tid], 0ull); } while (!(p & 1ull));
        atomicAdd(&s_prefix, (int)(p >> 1));
    }
    __syncthreads();
    const int pre = s_prefix;
    if (i < N_NODES) {
        int ex = pre + incl - v;
        g_off[i] = ex;
        g_cursor[i] = ex;
    }
    if (b == SCAN_BLOCKS - 1 && tid == 1023) g_off[N_NODES] = pre + incl;
}

__global__ __launch_bounds__(256) void fill_kernel(const void* __restrict__ eidx) {
    int is64 = detect_is64((const unsigned int*)eidx);
    int e = blockIdx.x * blockDim.x + threadIdx.x;
    if (e >= N_EDGES) return;
    int src, dst;
    if (is64) {
        const long long* p = (const long long*)eidx;
        src = (int)p[e];
        dst = (int)p[N_EDGES + e];
    } else {
        const int* p = (const int*)eidx;
        src = p[e];
        dst = p[N_EDGES + e];
    }
    int pos = atomicAdd(&g_cursor[dst], 1);
    g_csr[pos] = src;
}

// ---------------- gather + full-row int8 2-digit quantization ----------------
// one warp per node: agg half via CSR walk, x half direct, warp row-max scale.
__global__ __launch_bounds__(256) void gather_kernel(const float* __restrict__ x) {
    int node = blockIdx.x * 8 + (threadIdx.x >> 5);
    int lane = threadIdx.x & 31;

    uint32_t* rq0 = (uint32_t*)g_Aq0 + (size_t)node * (KTOT / 4);
    uint32_t* rq1 = (uint32_t*)g_Aq1 + (size_t)node * (KTOT / 4);

    if (node >= N_NODES) {     // zero padding rows
        uint4 z = make_uint4(0, 0, 0, 0);
        ((uint4*)rq0)[lane] = z;     // 32 lanes x 16B = 512B
        ((uint4*)rq1)[lane] = z;
        if (lane == 0) g_sA[node] = 0.f;
        return;
    }

    const int off0 = g_off[node];
    const int deg  = g_off[node + 1] - off0;
    const float4* xb = (const float4*)x;

    float v[16];
#pragma unroll
    for (int j = 0; j < 16; j++) v[j] = 0.f;

#pragma unroll 4
    for (int j = 0; j < deg; j++) {
        int src = g_csr[off0 + j];
        const float4* xs = xb + (size_t)src * 64;
        float4 v0 = xs[lane], v1 = xs[lane + 32];
        v[0] += v0.x; v[1] += v0.y; v[2] += v0.z; v[3] += v0.w;
        v[4] += v1.x; v[5] += v1.y; v[6] += v1.z; v[7] += v1.w;
    }
    const float inv = 1.f / fmaxf((float)deg, 1.f);
#pragma unroll
    for (int j = 0; j < 8; j++) v[j] *= inv;

    // x half (cols 256..511)
    {
        const float4* xs = xb + (size_t)node * 64;
        float4 v0 = xs[lane], v1 = xs[lane + 32];
        v[8]  = v0.x; v[9]  = v0.y; v[10] = v0.z; v[11] = v0.w;
        v[12] = v1.x; v[13] = v1.y; v[14] = v1.z; v[15] = v1.w;
    }

    // warp row max
    float mx = 0.f;
#pragma unroll
    for (int j = 0; j < 16; j++) mx = fmaxf(mx, fabsf(v[j]));
#pragma unroll
    for (int o = 16; o; o >>= 1) mx = fmaxf(mx, __shfl_xor_sync(0xffffffffu, mx, o));

    const float invs = (mx > 0.f) ? (127.f / mx) : 0.f;
    if (lane == 0) g_sA[node] = mx / 127.f;

    float rs[4];
    // word indices in the 128-word row: agg lo=lane, agg hi=lane+32, x lo=64+lane, x hi=96+lane
    rq0[lane]      = pack_q0(v + 0,  invs, rs); rq1[lane]      = pack_q1(rs);
    rq0[lane + 32] = pack_q0(v + 4,  invs, rs); rq1[lane + 32] = pack_q1(rs);
    rq0[lane + 64] = pack_q0(v + 8,  invs, rs); rq1[lane + 64] = pack_q1(rs);
    rq0[lane + 96] = pack_q0(v + 12, invs, rs); rq1[lane + 96] = pack_q1(rs);
}

// B'[n][k] = (k<256 ? Wl[k][n] : Wr[k-256][n]) -> per-n int8 2-digit quant
__global__ __launch_bounds__(256) void convB_kernel(
    const float* __restrict__ Wl, const float* __restrict__ Wr)
{
    int n = blockIdx.x * 8 + (threadIdx.x >> 5);
    int lane = threadIdx.x & 31;
    if (n >= D_HID) return;

    float v[16];
#pragma unroll
    for (int t = 0; t < 16; t++) {
        int k = lane * 16 + t;
        v[t] = (k < D_IN) ? Wl[(size_t)k * D_HID + n]
                          : Wr[(size_t)(k - D_IN) * D_HID + n];
    }
    float mx = 0.f;
#pragma unroll
    for (int t = 0; t < 16; t++) mx = fmaxf(mx, fabsf(v[t]));
#pragma unroll
    for (int o = 16; o; o >>= 1) mx = fmaxf(mx, __shfl_xor_sync(0xffffffffu, mx, o));

    const float invs = (mx > 0.f) ? (127.f / mx) : 0.f;
    if (lane == 0) g_sB[n] = mx / 127.f;

    uint32_t* rq0 = (uint32_t*)g_Bq0 + (size_t)n * (KTOT / 4);
    uint32_t* rq1 = (uint32_t*)g_Bq1 + (size_t)n * (KTOT / 4);
    float rs[4];
#pragma unroll
    for (int t = 0; t < 4; t++) {
        rq0[4 * lane + t] = pack_q0(v + 4 * t, invs, rs);
        rq1[4 * lane + t] = pack_q1(rs);
    }
}

// ---------------- int8 mma.sync GEMM ----------------
// out[i][n] = sA_i*sB_n*(hh + xx/254) + bias[n]
#define BM 128
#define BN 128
#define KC 128                              // 128 s8 per chunk = 128B rows
#define NCHUNK (KTOT / KC)                  // 4
#define TILE_BYTES (BM * KC)                // 16384 (128 rows x 128B, SW128)
#define SMEM_TOTAL (8 * TILE_BYTES)         // 131072

__device__ __forceinline__ void load_chunk(uint32_t sb, int s, int c, int row0, int col0, int tid) {
    const unsigned char* srcs[4];
    srcs[0] = g_Aq0 + (size_t)row0 * KTOT + c * KC;
    srcs[1] = g_Aq1 + (size_t)row0 * KTOT + c * KC;
    srcs[2] = g_Bq0 + (size_t)col0 * KTOT + c * KC;
    srcs[3] = g_Bq1 + (size_t)col0 * KTOT + c * KC;
#pragma unroll
    for (int i = 0; i < 16; i++) {
        int lin  = i * 256 + tid;        // 0..4095, 16B granules
        int tile = lin >> 10;
        int w    = lin & 1023;
        int r    = w >> 3;               // row 0..127
        int j    = w & 7;                // 16B col within 128B row
        const char* gp = (const char*)srcs[tile] + (size_t)r * KTOT + j * 16;
        uint32_t daddr = sb + (uint32_t)(s * 4 + tile) * TILE_BYTES + sw_off(r, j);
        asm volatile("cp.async.cg.shared.global [%0], [%1], 16;" :: "r"(daddr), "l"(gp) : "memory");
    }
    asm volatile("cp.async.commit_group;" ::: "memory");
}

__global__ __launch_bounds__(256, 1) void gemm_s8(
    const float* __restrict__ bias, float* __restrict__ out)
{
    extern __shared__ char smem[];
    uint32_t sb = smem_u32(smem);
    const int tid = threadIdx.x, wid = tid >> 5, lane = tid & 31;
    const int row0 = blockIdx.x * BM, col0 = blockIdx.y * BN;
    const int warp_m = (wid & 3) * 32;      // 0,32,64,96
    const int warp_n = (wid >> 2) * 64;     // 0,64

    int hh[2][8][4], xx[2][8][4];
#pragma unroll
    for (int mi = 0; mi < 2; mi++)
#pragma unroll
        for (int ni = 0; ni < 8; ni++)
#pragma unroll
            for (int j = 0; j < 4; j++) { hh[mi][ni][j] = 0; xx[mi][ni][j] = 0; }

    const int lmat = lane >> 3;             // matrix 0..3
    const int lrow = lane & 7;              // row within 8x8

    load_chunk(sb, 0, 0, row0, col0, tid);

    for (int c = 0; c < NCHUNK; c++) {
        const int s = c & 1;
        if (c + 1 < NCHUNK) {
            load_chunk(sb, s ^ 1, c + 1, row0, col0, tid);
            asm volatile("cp.async.wait_group 1;" ::: "memory");
        } else {
            asm volatile("cp.async.wait_group 0;" ::: "memory");
        }
        __syncthreads();

        const uint32_t tA0 = sb + (uint32_t)(s * 4 + 0) * TILE_BYTES;
        const uint32_t tA1 = sb + (uint32_t)(s * 4 + 1) * TILE_BYTES;
        const uint32_t tB0 = sb + (uint32_t)(s * 4 + 2) * TILE_BYTES;
        const uint32_t tB1 = sb + (uint32_t)(s * 4 + 3) * TILE_BYTES;

#pragma unroll
        for (int kk = 0; kk < 4; kk++) {    // 4 k32-steps per KC=128
            uint32_t a0f[2][4], a1f[2][4];
#pragma unroll
            for (int mi = 0; mi < 2; mi++) {
                int ra = warp_m + mi * 16 + (lmat & 1) * 8 + lrow;
                int ja = kk * 2 + (lmat >> 1);
                ldmatrix_x4(a0f[mi], tA0 + sw_off(ra, ja));
                ldmatrix_x4(a1f[mi], tA1 + sw_off(ra, ja));
            }
            int rb = warp_n + (lmat >> 1) * 8 + lrow;
            int jb = kk * 2 + (lmat & 1);
#pragma unroll
            for (int np = 0; np < 4; np++) {
                uint32_t b0f[4], b1f[4];
                ldmatrix_x4(b0f, tB0 + sw_off(rb + np * 16, jb));
                ldmatrix_x4(b1f, tB1 + sw_off(rb + np * 16, jb));
#pragma unroll
                for (int mi = 0; mi < 2; mi++) {
#pragma unroll
                    for (int q = 0; q < 2; q++) {
                        int ni = np * 2 + q;
                        mma_s8(hh[mi][ni], a0f[mi], b0f[2 * q], b0f[2 * q + 1]);
                        mma_s8(xx[mi][ni], a0f[mi], b1f[2 * q], b1f[2 * q + 1]);
                        mma_s8(xx[mi][ni], a1f[mi], b0f[2 * q], b0f[2 * q + 1]);
                    }
                }
            }
        }
        __syncthreads();
    }

    const int qrow = lane >> 2, qcol = (lane & 3) * 2;
    const float invc = 1.f / QC;
#pragma unroll
    for (int mi = 0; mi < 2; mi++) {
        int r0 = row0 + warp_m + mi * 16 + qrow;
        float sA0 = (r0 < N_NODES) ? g_sA[r0] : 0.f;
        float sA1 = (r0 + 8 < N_NODES) ? g_sA[r0 + 8] : 0.f;
#pragma unroll
        for (int ni = 0; ni < 8; ni++) {
            int cn = col0 + warp_n + ni * 8 + qcol;
            float2 bb = *(const float2*)(bias + cn);
            float sb0 = g_sB[cn], sb1 = g_sB[cn + 1];
            if (r0 < N_NODES) {
                float2 o;
                o.x = sA0 * sb0 * ((float)hh[mi][ni][0] + (float)xx[mi][ni][0] * invc) + bb.x;
                o.y = sA0 * sb1 * ((float)hh[mi][ni][1] + (float)xx[mi][ni][1] * invc) + bb.y;
                *(float2*)(out + (size_t)r0 * D_HID + cn) = o;
            }
            if (r0 + 8 < N_NODES) {
                float2 o;
                o.x = sA1 * sb0 * ((float)hh[mi][ni][2] + (float)xx[mi][ni][2] * invc) + bb.x;
                o.y = sA1 * sb1 * ((float)hh[mi][ni][3] + (float)xx[mi][ni][3] * invc) + bb.y;
                *(float2*)(out + (size_t)(r0 + 8) * D_HID + cn) = o;
            }
        }
    }
}

// ---------------- launch ----------------
extern "C" void kernel_launch(void* const* d_in, const int* in_sizes, int n_in,
                              void* d_out, int out_size) {
    const float* x    = (const float*)d_in[0];
    const void*  eidx = d_in[1];
    const float* Wl   = (const float*)d_in[2];
    const float* Wr   = (const float*)d_in[3];
    const float* bias = (const float*)d_in[4];
    float* out = (float*)d_out;

    cudaFuncSetAttribute(gemm_s8, cudaFuncAttributeMaxDynamicSharedMemorySize, SMEM_TOTAL);

    zero_kernel<<<(N_NODES + 255) / 256, 256>>>();
    hist_kernel<<<(N_EDGES + 255) / 256, 256>>>(eidx);
    scan_kernel<<<SCAN_BLOCKS, 1024>>>();
    fill_kernel<<<(N_EDGES + 255) / 256, 256>>>(eidx);
    convB_kernel<<<D_HID / 8, 256>>>(Wl, Wr);
    gather_kernel<<<M_PAD / 8, 256>>>(x);

    dim3 grid(M_PAD / BM, D_HID / BN);
    gemm_s8<<<grid, 256, SMEM_TOTAL>>>(bias, out);
}

// round 12
// speedup vs baseline: 2.3098x; 2.3098x over previous
#include <cuda_runtime.h>
#include <cuda_bf16.h>
#include <cstdint>

#define N_NODES 50000
#define D_IN    256
#define D_HID   512
#define N_EDGES 800000
#define KTOT    512           // fused K = D_IN (mean) + D_IN (x)
#define M_PAD   50048         // 391 * 128
#define SCAN_BLOCKS 49        // 49 * 1024 = 50176 >= N_NODES

// ---------------- scratch (device globals; allocation-free) ----------------
__device__ int   g_cnt_i[N_NODES];
__device__ int   g_off[N_NODES + 1];
__device__ int   g_cursor[N_NODES];
__device__ int   g_csr[N_EDGES];
__device__ unsigned long long g_pub[SCAN_BLOCKS];
__device__ __nv_bfloat16 g_Ahi[(size_t)M_PAD * KTOT];
__device__ __nv_bfloat16 g_Alo[(size_t)M_PAD * KTOT];
__device__ __nv_bfloat16 g_Bhi[(size_t)KTOT * KTOT];   // [N=512][K=512]
__device__ __nv_bfloat16 g_Blo[(size_t)KTOT * KTOT];

// ---------------- helpers ----------------
__device__ __forceinline__ uint32_t smem_u32(const void* p) {
    uint32_t a;
    asm("{ .reg .u64 t; cvta.to.shared.u64 t, %1; cvt.u32.u64 %0, t; }" : "=r"(a) : "l"(p));
    return a;
}
// swizzled offset within a 128-row x 128-byte tile: row r, 16B-chunk j
__device__ __forceinline__ uint32_t sw_off(int r, int j) {
    return (uint32_t)(r * 128 + ((j ^ (r & 7)) << 4));
}
__device__ __forceinline__ void ldmatrix_x4(uint32_t* f, uint32_t addr) {
    asm volatile("ldmatrix.sync.aligned.m8n8.x4.shared.b16 {%0,%1,%2,%3}, [%4];"
        : "=r"(f[0]), "=r"(f[1]), "=r"(f[2]), "=r"(f[3]) : "r"(addr));
}
__device__ __forceinline__ void mma_bf16(float* d, const uint32_t* a, uint32_t b0, uint32_t b1) {
    asm volatile("mma.sync.aligned.m16n8k16.row.col.f32.bf16.bf16.f32 "
        "{%0,%1,%2,%3}, {%4,%5,%6,%7}, {%8,%9}, {%0,%1,%2,%3};"
        : "+f"(d[0]), "+f"(d[1]), "+f"(d[2]), "+f"(d[3])
        : "r"(a[0]), "r"(a[1]), "r"(a[2]), "r"(a[3]), "r"(b0), "r"(b1));
}

// per-warp dtype detection: int64 edge_index has zero hi-words.
__device__ __forceinline__ int detect_is64(const unsigned int* __restrict__ e) {
    int lane = threadIdx.x & 31;
    unsigned w = (lane < 8) ? e[2 * lane + 1] : 0u;
    unsigned m = __ballot_sync(0xffffffffu, w != 0u);
    return (m & 0xFFu) == 0u;
}

// ---------------- CSR build ----------------
__global__ void zero_kernel() {
    int i = blockIdx.x * blockDim.x + threadIdx.x;
    if (i < N_NODES) g_cnt_i[i] = 0;
    if (i < SCAN_BLOCKS) g_pub[i] = 0ull;
}

__global__ __launch_bounds__(256) void hist_kernel(const void* __restrict__ eidx) {
    int is64 = detect_is64((const unsigned int*)eidx);
    int e = blockIdx.x * blockDim.x + threadIdx.x;
    if (e >= N_EDGES) return;
    int dst = is64 ? (int)((const long long*)eidx)[N_EDGES + e]
                   : ((const int*)eidx)[N_EDGES + e];
    atomicAdd(&g_cnt_i[dst], 1);
}

// single-pass scan with decoupled aggregate lookback (49 blocks co-resident)
__global__ __launch_bounds__(1024) void scan_kernel() {
    __shared__ int sdata[1024];
    __shared__ int s_prefix;
    const int tid = threadIdx.x, b = blockIdx.x;
    const int i = b * 1024 + tid;
    int v = (i < N_NODES) ? g_cnt_i[i] : 0;
    sdata[tid] = v;
    __syncthreads();
#pragma unroll
    for (int ofs = 1; ofs < 1024; ofs <<= 1) {
        int t = (tid >= ofs) ? sdata[tid - ofs] : 0;
        __syncthreads();
        sdata[tid] += t;
        __syncthreads();
    }
    const int incl = sdata[tid];
    const int agg  = sdata[1023];

    if (tid == 0) {
        s_prefix = 0;
        __threadfence();
        atomicExch(&g_pub[b], ((unsigned long long)(unsigned)agg << 1) | 1ull);
    }
    __syncthreads();
    if (tid < b) {
        unsigned long long p;
        do { p = atomicAdd(&g_pub[tid], 0ull); } while (!(p & 1ull));
        atomicAdd(&s_prefix, (int)(p >> 1));
    }
    __syncthreads();
    const int pre = s_prefix;
    if (i < N_NODES) {
        int ex = pre + incl - v;
        g_off[i] = ex;
        g_cursor[i] = ex;
    }
    if (b == SCAN_BLOCKS - 1 && tid == 1023) g_off[N_NODES] = pre + incl;
}

__global__ __launch_bounds__(256) void fill_kernel(const void* __restrict__ eidx) {
    int is64 = detect_is64((const unsigned int*)eidx);
    int e = blockIdx.x * blockDim.x + threadIdx.x;
    if (e >= N_EDGES) return;
    int src, dst;
    if (is64) {
        const long long* p = (const long long*)eidx;
        src = (int)p[e];
        dst = (int)p[N_EDGES + e];
    } else {
        const int* p = (const int*)eidx;
        src = p[e];
        dst = p[N_EDGES + e];
    }
    int pos = atomicAdd(&g_cursor[dst], 1);
    g_csr[pos] = src;
}

// ---------------- bf16 hi/lo split helper ----------------
__device__ __forceinline__ void write_hilo4(__nv_bfloat16* ph, __nv_bfloat16* pl,
                                            const float* v, float s) {
    union { __nv_bfloat16 h[4]; uint2 u; } hi, lo;
#pragma unroll
    for (int j = 0; j < 4; j++) {
        float f = v[j] * s;
        hi.h[j] = __float2bfloat16_rn(f);
        lo.h[j] = __float2bfloat16_rn(f - __bfloat162float(hi.h[j]));
    }
    *(uint2*)ph = hi.u;
    *(uint2*)pl = lo.u;
}

// ---------------- gather + bf16 split conversion (fused, full row) ----------------
__global__ __launch_bounds__(256) void gather_kernel(const float* __restrict__ x) {
    int node = blockIdx.x * 8 + (threadIdx.x >> 5);
    int lane = threadIdx.x & 31;

    __nv_bfloat16* rh = g_Ahi + (size_t)node * KTOT;
    __nv_bfloat16* rl = g_Alo + (size_t)node * KTOT;

    if (node >= N_NODES) {     // zero padding rows
        uint4 z = make_uint4(0, 0, 0, 0);
        ((uint4*)rh)[lane] = z; ((uint4*)rh)[lane + 32] = z;
        ((uint4*)rl)[lane] = z; ((uint4*)rl)[lane + 32] = z;
        return;
    }

    const int off0 = g_off[node];
    const int deg  = g_off[node + 1] - off0;
    const float4* xb = (const float4*)x;

    float a0[4] = {0, 0, 0, 0}, a1[4] = {0, 0, 0, 0};
#pragma unroll 4
    for (int j = 0; j < deg; j++) {
        int src = g_csr[off0 + j];
        const float4* xs = xb + (size_t)src * 64;
        float4 v0 = xs[lane], v1 = xs[lane + 32];
        a0[0] += v0.x; a0[1] += v0.y; a0[2] += v0.z; a0[3] += v0.w;
        a1[0] += v1.x; a1[1] += v1.y; a1[2] += v1.z; a1[3] += v1.w;
    }
    float inv = 1.f / fmaxf((float)deg, 1.f);
    write_hilo4(rh + 4 * lane, rl + 4 * lane, a0, inv);
    write_hilo4(rh + 4 * (lane + 32), rl + 4 * (lane + 32), a1, inv);

    // x-half (cols 256..511)
    const float4* xs = xb + (size_t)node * 64;
    float4 v0 = xs[lane], v1 = xs[lane + 32];
    float b0[4] = {v0.x, v0.y, v0.z, v0.w};
    float b1[4] = {v1.x, v1.y, v1.z, v1.w};
    write_hilo4(rh + D_IN + 4 * lane, rl + D_IN + 4 * lane, b0, 1.f);
    write_hilo4(rh + D_IN + 4 * (lane + 32), rl + D_IN + 4 * (lane + 32), b1, 1.f);
}

// B'[n][k] = (k<256 ? Wl[k][n] : Wr[k-256][n]) -> bf16 hi/lo (K-major rows)
__global__ __launch_bounds__(256) void convB_kernel(
    const float* __restrict__ Wl, const float* __restrict__ Wr)
{
    int i = blockIdx.x * blockDim.x + threadIdx.x;
    if (i >= KTOT * KTOT) return;
    int n = i >> 9, k = i & 511;
    float w = (k < D_IN) ? Wl[(size_t)k * D_HID + n] : Wr[(size_t)(k - D_IN) * D_HID + n];
    __nv_bfloat16 hi = __float2bfloat16_rn(w);
    __nv_bfloat16 lo = __float2bfloat16_rn(w - __bfloat162float(hi));
    g_Bhi[i] = hi;
    g_Blo[i] = lo;
}

// ---------------- mma.sync GEMM: out = A'@B'^T + bias ----------------
// Grid = (cols, rows): the 4 column-CTAs of one row tile are adjacent in
// schedule order, so they share the A tile through L2 (A DRAM 410MB -> ~110MB).
#define BM 128
#define BN 128
#define KC 64
#define NCHUNK (KTOT / KC)                  // 8
#define TILE_BYTES (BM * KC * 2)            // 16384 (128 rows x 128B, SW128)
#define SMEM_TOTAL (8 * TILE_BYTES)         // 131072

__device__ __forceinline__ void load_chunk(uint32_t sb, int s, int c, int row0, int col0, int tid) {
    const __nv_bfloat16* srcs[4];
    srcs[0] = g_Ahi + (size_t)row0 * KTOT + c * KC;
    srcs[1] = g_Alo + (size_t)row0 * KTOT + c * KC;
    srcs[2] = g_Bhi + (size_t)col0 * KTOT + c * KC;
    srcs[3] = g_Blo + (size_t)col0 * KTOT + c * KC;
#pragma unroll
    for (int i = 0; i < 16; i++) {
        int lin  = i * 256 + tid;        // 0..4095, 16B granules
        int tile = lin >> 10;
        int w    = lin & 1023;
        int r    = w >> 3;               // row 0..127
        int j    = w & 7;                // 16B col within 128B row
        const char* gp = (const char*)srcs[tile] + (size_t)r * (KTOT * 2) + j * 16;
        uint32_t daddr = sb + (uint32_t)(s * 4 + tile) * TILE_BYTES + sw_off(r, j);
        asm volatile("cp.async.cg.shared.global [%0], [%1], 16;" :: "r"(daddr), "l"(gp) : "memory");
    }
    asm volatile("cp.async.commit_group;" ::: "memory");
}

__global__ __launch_bounds__(256, 1) void gemm_mma(
    const float* __restrict__ bias, float* __restrict__ out)
{
    extern __shared__ char smem[];
    uint32_t sb = smem_u32(smem);
    const int tid = threadIdx.x, wid = tid >> 5, lane = tid & 31;
    const int row0 = blockIdx.y * BM, col0 = blockIdx.x * BN;   // grid swapped
    const int warp_m = (wid & 3) * 32;      // 0,32,64,96
    const int warp_n = (wid >> 2) * 64;     // 0,64

    float acc[2][8][4];
#pragma unroll
    for (int mi = 0; mi < 2; mi++)
#pragma unroll
        for (int ni = 0; ni < 8; ni++)
#pragma unroll
            for (int j = 0; j < 4; j++) acc[mi][ni][j] = 0.f;

    const int lmat = lane >> 3;             // matrix 0..3
    const int lrow = lane & 7;              // row within 8x8

    load_chunk(sb, 0, 0, row0, col0, tid);

    for (int c = 0; c < NCHUNK; c++) {
        const int s = c & 1;
        if (c + 1 < NCHUNK) {
            load_chunk(sb, s ^ 1, c + 1, row0, col0, tid);
            asm volatile("cp.async.wait_group 1;" ::: "memory");
        } else {
            asm volatile("cp.async.wait_group 0;" ::: "memory");
        }
        __syncthreads();

        const uint32_t tAh = sb + (uint32_t)(s * 4 + 0) * TILE_BYTES;
        const uint32_t tAl = sb + (uint32_t)(s * 4 + 1) * TILE_BYTES;
        const uint32_t tBh = sb + (uint32_t)(s * 4 + 2) * TILE_BYTES;
        const uint32_t tBl = sb + (uint32_t)(s * 4 + 3) * TILE_BYTES;

#pragma unroll
        for (int kk = 0; kk < 4; kk++) {    // 4 k16-steps per KC=64
            uint32_t ah[2][4], al[2][4];
#pragma unroll
            for (int mi = 0; mi < 2; mi++) {
                int ra = warp_m + mi * 16 + (lmat & 1) * 8 + lrow;
                int ja = kk * 2 + (lmat >> 1);
                ldmatrix_x4(ah[mi], tAh + sw_off(ra, ja));
                ldmatrix_x4(al[mi], tAl + sw_off(ra, ja));
            }
            int rb = warp_n + (lmat >> 1) * 8 + lrow;
            int jb = kk * 2 + (lmat & 1);
#pragma unroll
            for (int np = 0; np < 4; np++) {
                uint32_t bh[4], bl[4];
                ldmatrix_x4(bh, tBh + sw_off(rb + np * 16, jb));
                ldmatrix_x4(bl, tBl + sw_off(rb + np * 16, jb));
#pragma unroll
                for (int mi = 0; mi < 2; mi++) {
#pragma unroll
                    for (int q = 0; q < 2; q++) {
                        int ni = np * 2 + q;
                        mma_bf16(acc[mi][ni], ah[mi], bh[2 * q], bh[2 * q + 1]);
                        mma_bf16(acc[mi][ni], ah[mi], bl[2 * q], bl[2 * q + 1]);
                        mma_bf16(acc[mi][ni], al[mi], bh[2 * q], bh[2 * q + 1]);
                    }
                }
            }
        }
        __syncthreads();
    }

    const int qrow = lane >> 2, qcol = (lane & 3) * 2;
#pragma unroll
    for (int mi = 0; mi < 2; mi++) {
        int r0 = row0 + warp_m + mi * 16 + qrow;
#pragma unroll
        for (int ni = 0; ni < 8; ni++) {
            int cn = col0 + warp_n + ni * 8 + qcol;
            float2 bb = *(const float2*)(bias + cn);
            if (r0 < N_NODES) {
                float2 o0 = make_float2(acc[mi][ni][0] + bb.x, acc[mi][ni][1] + bb.y);
                *(float2*)(out + (size_t)r0 * D_HID + cn) = o0;
            }
            if (r0 + 8 < N_NODES) {
                float2 o1 = make_float2(acc[mi][ni][2] + bb.x, acc[mi][ni][3] + bb.y);
                *(float2*)(out + (size_t)(r0 + 8) * D_HID + cn) = o1;
            }
        }
    }
}

// ---------------- launch ----------------
extern "C" void kernel_launch(void* const* d_in, const int* in_sizes, int n_in,
                              void* d_out, int out_size) {
    const float* x    = (const float*)d_in[0];
    const void*  eidx = d_in[1];
    const float* Wl   = (const float*)d_in[2];
    const float* Wr   = (const float*)d_in[3];
    const float* bias = (const float*)d_in[4];
    float* out = (float*)d_out;

    cudaFuncSetAttribute(gemm_mma, cudaFuncAttributeMaxDynamicSharedMemorySize, SMEM_TOTAL);

    zero_kernel<<<(N_NODES + 255) / 256, 256>>>();
    hist_kernel<<<(N_EDGES + 255) / 256, 256>>>(eidx);
    scan_kernel<<<SCAN_BLOCKS, 1024>>>();
    fill_kernel<<<(N_EDGES + 255) / 256, 256>>>(eidx);
    convB_kernel<<<(KTOT * KTOT + 255) / 256, 256>>>(Wl, Wr);
    gather_kernel<<<M_PAD / 8, 256>>>(x);

    dim3 grid(D_HID / BN, M_PAD / BM);      // (cols, rows) — L2 A-reuse
    gemm_mma<<<grid, 256, SMEM_TOTAL>>>(bias, out);
}

// round 13
// speedup vs baseline: 4.4179x; 1.9127x over previous
#include <cuda_runtime.h>
#include <cuda_fp16.h>
#include <cstdint>

#define N_NODES 50000
#define D_IN    256
#define D_HID   512
#define N_EDGES 800000
#define KTOT    512           // fused K = D_IN (mean) + D_IN (x)
#define M_PAD   50048         // 391 * 128
#define SCAN_BLOCKS 49        // 49 * 1024 = 50176 >= N_NODES

// ---------------- scratch (device globals; allocation-free) ----------------
__device__ int   g_cnt_i[N_NODES];
__device__ int   g_off[N_NODES + 1];
__device__ int   g_cursor[N_NODES];
__device__ int   g_csr[N_EDGES];
__device__ unsigned long long g_pub[SCAN_BLOCKS];
__device__ __half g_xh[(size_t)N_NODES * D_IN];        // fp16 copy of x
__device__ __half g_A[(size_t)M_PAD * KTOT];           // [mean | x] fp16
__device__ __half g_B[(size_t)D_HID * KTOT];           // [n][k] fp16

// ---------------- helpers ----------------
__device__ __forceinline__ uint32_t smem_u32(const void* p) {
    uint32_t a;
    asm("{ .reg .u64 t; cvta.to.shared.u64 t, %1; cvt.u32.u64 %0, t; }" : "=r"(a) : "l"(p));
    return a;
}
// swizzled offset within a 128-row x 128-byte tile: row r, 16B-chunk j
__device__ __forceinline__ uint32_t sw_off(int r, int j) {
    return (uint32_t)(r * 128 + ((j ^ (r & 7)) << 4));
}
__device__ __forceinline__ void ldmatrix_x4(uint32_t* f, uint32_t addr) {
    asm volatile("ldmatrix.sync.aligned.m8n8.x4.shared.b16 {%0,%1,%2,%3}, [%4];"
        : "=r"(f[0]), "=r"(f[1]), "=r"(f[2]), "=r"(f[3]) : "r"(addr));
}
__device__ __forceinline__ void mma_f16(float* d, const uint32_t* a, uint32_t b0, uint32_t b1) {
    asm volatile("mma.sync.aligned.m16n8k16.row.col.f32.f16.f16.f32 "
        "{%0,%1,%2,%3}, {%4,%5,%6,%7}, {%8,%9}, {%0,%1,%2,%3};"
        : "+f"(d[0]), "+f"(d[1]), "+f"(d[2]), "+f"(d[3])
        : "r"(a[0]), "r"(a[1]), "r"(a[2]), "r"(a[3]), "r"(b0), "r"(b1));
}

// per-warp dtype detection: int64 edge_index has zero hi-words.
__device__ __forceinline__ int detect_is64(const unsigned int* __restrict__ e) {
    int lane = threadIdx.x & 31;
    unsigned w = (lane < 8) ? e[2 * lane + 1] : 0u;
    unsigned m = __ballot_sync(0xffffffffu, w != 0u);
    return (m & 0xFFu) == 0u;
}

// ---------------- CSR build ----------------
__global__ void zero_kernel() {
    int i = blockIdx.x * blockDim.x + threadIdx.x;
    if (i < N_NODES) g_cnt_i[i] = 0;
    if (i < SCAN_BLOCKS) g_pub[i] = 0ull;
}

__global__ __launch_bounds__(256) void hist_kernel(const void* __restrict__ eidx) {
    int is64 = detect_is64((const unsigned int*)eidx);
    int e = blockIdx.x * blockDim.x + threadIdx.x;
    if (e >= N_EDGES) return;
    int dst = is64 ? (int)((const long long*)eidx)[N_EDGES + e]
                   : ((const int*)eidx)[N_EDGES + e];
    atomicAdd(&g_cnt_i[dst], 1);
}

// single-pass scan with decoupled aggregate lookback (49 blocks co-resident)
__global__ __launch_bounds__(1024) void scan_kernel() {
    __shared__ int sdata[1024];
    __shared__ int s_prefix;
    const int tid = threadIdx.x, b = blockIdx.x;
    const int i = b * 1024 + tid;
    int v = (i < N_NODES) ? g_cnt_i[i] : 0;
    sdata[tid] = v;
    __syncthreads();
#pragma unroll
    for (int ofs = 1; ofs < 1024; ofs <<= 1) {
        int t = (tid >= ofs) ? sdata[tid - ofs] : 0;
        __syncthreads();
        sdata[tid] += t;
        __syncthreads();
    }
    const int incl = sdata[tid];
    const int agg  = sdata[1023];

    if (tid == 0) {
        s_prefix = 0;
        __threadfence();
        atomicExch(&g_pub[b], ((unsigned long long)(unsigned)agg << 1) | 1ull);
    }
    __syncthreads();
    if (tid < b) {
        unsigned long long p;
        do { p = atomicAdd(&g_pub[tid], 0ull); } while (!(p & 1ull));
        atomicAdd(&s_prefix, (int)(p >> 1));
    }
    __syncthreads();
    const int pre = s_prefix;
    if (i < N_NODES) {
        int ex = pre + incl - v;
        g_off[i] = ex;
        g_cursor[i] = ex;
    }
    if (b == SCAN_BLOCKS - 1 && tid == 1023) g_off[N_NODES] = pre + incl;
}

__global__ __launch_bounds__(256) void fill_kernel(const void* __restrict__ eidx) {
    int is64 = detect_is64((const unsigned int*)eidx);
    int e = blockIdx.x * blockDim.x + threadIdx.x;
    if (e >= N_EDGES) return;
    int src, dst;
    if (is64) {
        const long long* p = (const long long*)eidx;
        src = (int)p[e];
        dst = (int)p[N_EDGES + e];
    } else {
        const int* p = (const int*)eidx;
        src = p[e];
        dst = p[N_EDGES + e];
    }
    int pos = atomicAdd(&g_cursor[dst], 1);
    g_csr[pos] = src;
}

// ---------------- x -> fp16 ----------------
__global__ __launch_bounds__(256) void convX_kernel(const float* __restrict__ x) {
    int i = blockIdx.x * blockDim.x + threadIdx.x;      // 8 elems per thread
    const int total = N_NODES * D_IN / 8;
    if (i >= total) return;
    const float4* p = (const float4*)x + 2 * (size_t)i;
    float4 a = p[0], b = p[1];
    union { __half h[8]; uint4 u; } o;
    o.h[0] = __float2half_rn(a.x); o.h[1] = __float2half_rn(a.y);
    o.h[2] = __float2half_rn(a.z); o.h[3] = __float2half_rn(a.w);
    o.h[4] = __float2half_rn(b.x); o.h[5] = __float2half_rn(b.y);
    o.h[6] = __float2half_rn(b.z); o.h[7] = __float2half_rn(b.w);
    ((uint4*)g_xh)[i] = o.u;
}

// B[n][k] = (k<256 ? Wl[k][n] : Wr[k-256][n]) fp16, K-major rows
__global__ __launch_bounds__(256) void convB_kernel(
    const float* __restrict__ Wl, const float* __restrict__ Wr)
{
    int i = blockIdx.x * blockDim.x + threadIdx.x;
    if (i >= KTOT * KTOT) return;
    int n = i >> 9, k = i & 511;
    float w = (k < D_IN) ? Wl[(size_t)k * D_HID + n] : Wr[(size_t)(k - D_IN) * D_HID + n];
    g_B[i] = __float2half_rn(w);
}

// ---------------- gather: warp per node, fp16 reads, fp16 writes ----------------
__global__ __launch_bounds__(256) void gather_kernel() {
    int node = blockIdx.x * 8 + (threadIdx.x >> 5);
    int lane = threadIdx.x & 31;

    uint4* row = (uint4*)(g_A + (size_t)node * KTOT);   // 64 uint4 per row

    if (node >= N_NODES) {     // zero padding rows
        uint4 z = make_uint4(0, 0, 0, 0);
        row[lane] = z;
        row[lane + 32] = z;
        return;
    }

    const int off0 = g_off[node];
    const int deg  = g_off[node + 1] - off0;
    const uint4* xb = (const uint4*)g_xh;               // 32 uint4 per x row

    float acc[8];
#pragma unroll
    for (int j = 0; j < 8; j++) acc[j] = 0.f;

#pragma unroll 4
    for (int j = 0; j < deg; j++) {
        int src = g_csr[off0 + j];
        uint4 v = xb[(size_t)src * 32 + lane];
        const __half2* h2 = (const __half2*)&v;
#pragma unroll
        for (int t = 0; t < 4; t++) {
            float2 f = __half22float2(h2[t]);
            acc[2 * t]     += f.x;
            acc[2 * t + 1] += f.y;
        }
    }
    const float inv = 1.f / fmaxf((float)deg, 1.f);
    union { __half h[8]; uint4 u; } o;
#pragma unroll
    for (int j = 0; j < 8; j++) o.h[j] = __float2half_rn(acc[j] * inv);
    row[lane] = o.u;                                    // mean half
    row[lane + 32] = xb[(size_t)node * 32 + lane];      // x half: direct copy
}

// ---------------- fp16 mma.sync GEMM: out = A@B^T + bias ----------------
#define BM 128
#define BN 128
#define KC 64
#define NCHUNK (KTOT / KC)                  // 8
#define TILE_BYTES (BM * KC * 2)            // 16384 (128 rows x 128B, SW128)
#define SMEM_TOTAL (4 * TILE_BYTES)         // 65536 -> 2+ CTAs/SM

__device__ __forceinline__ void load_chunk(uint32_t sb, int s, int c, int row0, int col0, int tid) {
    const __half* srcs[2];
    srcs[0] = g_A + (size_t)row0 * KTOT + c * KC;
    srcs[1] = g_B + (size_t)col0 * KTOT + c * KC;
#pragma unroll
    for (int i = 0; i < 8; i++) {
        int lin  = i * 256 + tid;        // 0..2047, 16B granules
        int tile = lin >> 10;
        int w    = lin & 1023;
        int r    = w >> 3;               // row 0..127
        int j    = w & 7;                // 16B col within 128B row
        const char* gp = (const char*)srcs[tile] + (size_t)r * (KTOT * 2) + j * 16;
        uint32_t daddr = sb + (uint32_t)(s * 2 + tile) * TILE_BYTES + sw_off(r, j);
        asm volatile("cp.async.cg.shared.global [%0], [%1], 16;" :: "r"(daddr), "l"(gp) : "memory");
    }
    asm volatile("cp.async.commit_group;" ::: "memory");
}

__global__ __launch_bounds__(256, 2) void gemm_f16(
    const float* __restrict__ bias, float* __restrict__ out)
{
    extern __shared__ char smem[];
    uint32_t sb = smem_u32(smem);
    const int tid = threadIdx.x, wid = tid >> 5, lane = tid & 31;
    const int row0 = blockIdx.y * BM, col0 = blockIdx.x * BN;
    const int warp_m = (wid & 3) * 32;      // 0,32,64,96
    const int warp_n = (wid >> 2) * 64;     // 0,64

    float acc[2][8][4];
#pragma unroll
    for (int mi = 0; mi < 2; mi++)
#pragma unroll
        for (int ni = 0; ni < 8; ni++)
#pragma unroll
            for (int j = 0; j < 4; j++) acc[mi][ni][j] = 0.f;

    const int lmat = lane >> 3;             // matrix 0..3
    const int lrow = lane & 7;              // row within 8x8

    load_chunk(sb, 0, 0, row0, col0, tid);

    for (int c = 0; c < NCHUNK; c++) {
        const int s = c & 1;
        if (c + 1 < NCHUNK) {
            load_chunk(sb, s ^ 1, c + 1, row0, col0, tid);
            asm volatile("cp.async.wait_group 1;" ::: "memory");
        } else {
            asm volatile("cp.async.wait_group 0;" ::: "memory");
        }
        __syncthreads();

        const uint32_t tA = sb + (uint32_t)(s * 2 + 0) * TILE_BYTES;
        const uint32_t tB = sb + (uint32_t)(s * 2 + 1) * TILE_BYTES;

#pragma unroll
        for (int kk = 0; kk < 4; kk++) {    // 4 k16-steps per KC=64
            uint32_t af[2][4];
#pragma unroll
            for (int mi = 0; mi < 2; mi++) {
                int ra = warp_m + mi * 16 + (lmat & 1) * 8 + lrow;
                int ja = kk * 2 + (lmat >> 1);
                ldmatrix_x4(af[mi], tA + sw_off(ra, ja));
            }
            int rb = warp_n + (lmat >> 1) * 8 + lrow;
            int jb = kk * 2 + (lmat & 1);
#pragma unroll
            for (int np = 0; np < 4; np++) {
                uint32_t bf[4];
                ldmatrix_x4(bf, tB + sw_off(rb + np * 16, jb));
#pragma unroll
                for (int mi = 0; mi < 2; mi++) {
#pragma unroll
                    for (int q = 0; q < 2; q++) {
                        mma_f16(acc[mi][np * 2 + q], af[mi], bf[2 * q], bf[2 * q + 1]);
                    }
                }
            }
        }
        __syncthreads();
    }

    const int qrow = lane >> 2, qcol = (lane & 3) * 2;
#pragma unroll
    for (int mi = 0; mi < 2; mi++) {
        int r0 = row0 + warp_m + mi * 16 + qrow;
#pragma unroll
        for (int ni = 0; ni < 8; ni++) {
            int cn = col0 + warp_n + ni * 8 + qcol;
            float2 bb = *(const float2*)(bias + cn);
            if (r0 < N_NODES) {
                float2 o0 = make_float2(acc[mi][ni][0] + bb.x, acc[mi][ni][1] + bb.y);
                *(float2*)(out + (size_t)r0 * D_HID + cn) = o0;
            }
            if (r0 + 8 < N_NODES) {
                float2 o1 = make_float2(acc[mi][ni][2] + bb.x, acc[mi][ni][3] + bb.y);
                *(float2*)(out + (size_t)(r0 + 8) * D_HID + cn) = o1;
            }
        }
    }
}

// ---------------- launch ----------------
extern "C" void kernel_launch(void* const* d_in, const int* in_sizes, int n_in,
                              void* d_out, int out_size) {
    const float* x    = (const float*)d_in[0];
    const void*  eidx = d_in[1];
    const float* Wl   = (const float*)d_in[2];
    const float* Wr   = (const float*)d_in[3];
    const float* bias = (const float*)d_in[4];
    float* out = (float*)d_out;

    cudaFuncSetAttribute(gemm_f16, cudaFuncAttributeMaxDynamicSharedMemorySize, SMEM_TOTAL);

    zero_kernel<<<(N_NODES + 255) / 256, 256>>>();
    hist_kernel<<<(N_EDGES + 255) / 256, 256>>>(eidx);
    scan_kernel<<<SCAN_BLOCKS, 1024>>>();
    fill_kernel<<<(N_EDGES + 255) / 256, 256>>>(eidx);
    convX_kernel<<<(N_NODES * D_IN / 8 + 255) / 256, 256>>>(x);
    convB_kernel<<<(KTOT * KTOT + 255) / 256, 256>>>(Wl, Wr);
    gather_kernel<<<M_PAD / 8, 256>>>();

    dim3 grid(D_HID / BN, M_PAD / BM);      // (cols, rows) — L2 A-reuse
    gemm_f16<<<grid, 256, SMEM_TOTAL>>>(bias, out);
}

// round 16
// speedup vs baseline: 4.4926x; 1.0169x over previous
#include <cuda_runtime.h>
#include <cuda_fp16.h>
#include <cstdint>

#define N_NODES 50000
#define D_IN    256
#define D_HID   512
#define N_EDGES 800000
#define KTOT    512           // fused K = D_IN (mean) + D_IN (x)
#define M_PAD   50048         // 391 * 128
#define SCAN_BLOCKS 49        // 49 * 1024 = 50176 >= N_NODES

// edge-kernel shape: 4 edges per thread
#define EDGE_THREADS (N_EDGES / 4)          // 200000
#define EDGE_BLOCKS  ((EDGE_THREADS + 255) / 256)   // 782

// prep_kernel block ranges
#define PREP_CONVX_BLOCKS 6250              // 6250*256 threads * 8 elems = 12.8M elems
#define PREP_CONVB_BLOCKS 512               // 512*256*2 = 262,144 elems
#define PREP_ZERO_BLOCKS  196               // 196*256 >= 50,000
#define PREP_BLOCKS (PREP_CONVX_BLOCKS + PREP_CONVB_BLOCKS + PREP_ZERO_BLOCKS)

// ---------------- scratch (device globals; allocation-free) ----------------
__device__ int   g_cnt_i[N_NODES];
__device__ int   g_off[N_NODES + 1];
__device__ int   g_cursor[N_NODES];
__device__ int   g_csr[N_EDGES];
__device__ unsigned long long g_pub[SCAN_BLOCKS];
__device__ __half g_xh[(size_t)N_NODES * D_IN];        // fp16 copy of x
__device__ __half g_A[(size_t)M_PAD * KTOT];           // [mean | x] fp16
__device__ __half g_B[(size_t)D_HID * KTOT];           // [n][k] fp16

// ---------------- helpers ----------------
__device__ __forceinline__ uint32_t smem_u32(const void* p) {
    uint32_t a;
    asm("{ .reg .u64 t; cvta.to.shared.u64 t, %1; cvt.u32.u64 %0, t; }" : "=r"(a) : "l"(p));
    return a;
}
// swizzled offset within a 128-row x 128-byte tile: row r, 16B-chunk j
__device__ __forceinline__ uint32_t sw_off(int r, int j) {
    return (uint32_t)(r * 128 + ((j ^ (r & 7)) << 4));
}
__device__ __forceinline__ void ldmatrix_x4(uint32_t* f, uint32_t addr) {
    asm volatile("ldmatrix.sync.aligned.m8n8.x4.shared.b16 {%0,%1,%2,%3}, [%4];"
        : "=r"(f[0]), "=r"(f[1]), "=r"(f[2]), "=r"(f[3]) : "r"(addr));
}
__device__ __forceinline__ void mma_f16(float* d, const uint32_t* a, uint32_t b0, uint32_t b1) {
    asm volatile("mma.sync.aligned.m16n8k16.row.col.f32.f16.f16.f32 "
        "{%0,%1,%2,%3}, {%4,%5,%6,%7}, {%8,%9}, {%0,%1,%2,%3};"
        : "+f"(d[0]), "+f"(d[1]), "+f"(d[2]), "+f"(d[3])
        : "r"(a[0]), "r"(a[1]), "r"(a[2]), "r"(a[3]), "r"(b0), "r"(b1));
}

// per-warp dtype detection: int64 edge_index has zero hi-words.
__device__ __forceinline__ int detect_is64(const unsigned int* __restrict__ e) {
    int lane = threadIdx.x & 31;
    unsigned w = (lane < 8) ? e[2 * lane + 1] : 0u;
    unsigned m = __ballot_sync(0xffffffffu, w != 0u);
    return (m & 0xFFu) == 0u;
}

// ---------------- prep: convX + convB + zero (fused, independent work) ------
__global__ __launch_bounds__(256) void prep_kernel(
    const float* __restrict__ x, const float* __restrict__ Wl,
    const float* __restrict__ Wr)
{
    int blk = blockIdx.x;
    if (blk < PREP_CONVX_BLOCKS) {
        // x -> fp16, 8 elems per thread
        int i = blk * 256 + threadIdx.x;
        const int total = N_NODES * D_IN / 8;          // 1,600,000
        if (i >= total) return;
        const float4* p = (const float4*)x + 2 * (size_t)i;
        float4 a = p[0], b = p[1];
        union { __half h[8]; uint4 u; } o;
        o.h[0] = __float2half_rn(a.x); o.h[1] = __float2half_rn(a.y);
        o.h[2] = __float2half_rn(a.z); o.h[3] = __float2half_rn(a.w);
        o.h[4] = __float2half_rn(b.x); o.h[5] = __float2half_rn(b.y);
        o.h[6] = __float2half_rn(b.z); o.h[7] = __float2half_rn(b.w);
        ((uint4*)g_xh)[i] = o.u;
    } else if (blk < PREP_CONVX_BLOCKS + PREP_CONVB_BLOCKS) {
        // B[n][k] = (k<256 ? Wl[k][n] : Wr[k-256][n]) fp16, 2 elems per thread
        int i0 = (blk - PREP_CONVX_BLOCKS) * 512 + threadIdx.x * 2;
#pragma unroll
        for (int t = 0; t < 2; t++) {
            int i = i0 + t;
            int n = i >> 9, k = i & 511;
            float w = (k < D_IN) ? Wl[(size_t)k * D_HID + n]
                                 : Wr[(size_t)(k - D_IN) * D_HID + n];
            g_B[i] = __float2half_rn(w);
        }
    } else {
        // zero counters + scan publications
        int i = (blk - PREP_CONVX_BLOCKS - PREP_CONVB_BLOCKS) * 256 + threadIdx.x;
        if (i < N_NODES) g_cnt_i[i] = 0;
        if (i < SCAN_BLOCKS) g_pub[i] = 0ull;
    }
}

// ---------------- CSR build (4 edges per thread for MLP) ----------------
// Mapping e = t + k*EDGE_THREADS is a bijection onto [0, N_EDGES) ONLY for
// t < EDGE_THREADS — surplus tail threads must do nothing (R15 bug).
__global__ __launch_bounds__(256) void hist_kernel(const void* __restrict__ eidx) {
    int is64 = detect_is64((const unsigned int*)eidx);
    int t = blockIdx.x * blockDim.x + threadIdx.x;
    if (t >= EDGE_THREADS) return;
#pragma unroll
    for (int k = 0; k < 4; k++) {
        int e = t + k * EDGE_THREADS;
        int dst = is64 ? (int)((const long long*)eidx)[N_EDGES + e]
                       : ((const int*)eidx)[N_EDGES + e];
        atomicAdd(&g_cnt_i[dst], 1);
    }
}

// single-pass scan with decoupled aggregate lookback (49 blocks co-resident)
__global__ __launch_bounds__(1024) void scan_kernel() {
    __shared__ int sdata[1024];
    __shared__ int s_prefix;
    const int tid = threadIdx.x, b = blockIdx.x;
    const int i = b * 1024 + tid;
    int v = (i < N_NODES) ? g_cnt_i[i] : 0;
    sdata[tid] = v;
    __syncthreads();
#pragma unroll
    for (int ofs = 1; ofs < 1024; ofs <<= 1) {
        int t = (tid >= ofs) ? sdata[tid - ofs] : 0;
        __syncthreads();
        sdata[tid] += t;
        __syncthreads();
    }
    const int incl = sdata[tid];
    const int agg  = sdata[1023];

    if (tid == 0) {
        s_prefix = 0;
        __threadfence();
        atomicExch(&g_pub[b], ((unsigned long long)(unsigned)agg << 1) | 1ull);
    }
    __syncthreads();
    if (tid < b) {
        unsigned long long p;
        do { p = atomicAdd(&g_pub[tid], 0ull); } while (!(p & 1ull));
        atomicAdd(&s_prefix, (int)(p >> 1));
    }
    __syncthreads();
    const int pre = s_prefix;
    if (i < N_NODES) {
        int ex = pre + incl - v;
        g_off[i] = ex;
        g_cursor[i] = ex;
    }
    if (b == SCAN_BLOCKS - 1 && tid == 1023) g_off[N_NODES] = pre + incl;
}

__global__ __launch_bounds__(256) void fill_kernel(const void* __restrict__ eidx) {
    int is64 = detect_is64((const unsigned int*)eidx);
    int t = blockIdx.x * blockDim.x + threadIdx.x;
    if (t >= EDGE_THREADS) return;
#pragma unroll
    for (int k = 0; k < 4; k++) {
        int e = t + k * EDGE_THREADS;
        int src, dst;
        if (is64) {
            const long long* p = (const long long*)eidx;
            src = (int)p[e];
            dst = (int)p[N_EDGES + e];
        } else {
            const int* p = (const int*)eidx;
            src = p[e];
            dst = p[N_EDGES + e];
        }
        int pos = atomicAdd(&g_cursor[dst], 1);
        g_csr[pos] = src;
    }
}

// ---------------- gather: warp per node, fp16 reads, fp16 writes ----------------
__global__ __launch_bounds__(256) void gather_kernel() {
    int node = blockIdx.x * 8 + (threadIdx.x >> 5);
    int lane = threadIdx.x & 31;

    uint4* row = (uint4*)(g_A + (size_t)node * KTOT);   // 64 uint4 per row

    if (node >= N_NODES) {     // zero padding rows
        uint4 z = make_uint4(0, 0, 0, 0);
        row[lane] = z;
        row[lane + 32] = z;
        return;
    }

    const int off0 = g_off[node];
    const int deg  = g_off[node + 1] - off0;
    const uint4* xb = (const uint4*)g_xh;               // 32 uint4 per x row

    float acc[8];
#pragma unroll
    for (int j = 0; j < 8; j++) acc[j] = 0.f;

#pragma unroll 4
    for (int j = 0; j < deg; j++) {
        int src = g_csr[off0 + j];
        uint4 v = xb[(size_t)src * 32 + lane];
        const __half2* h2 = (const __half2*)&v;
#pragma unroll
        for (int t = 0; t < 4; t++) {
            float2 f = __half22float2(h2[t]);
            acc[2 * t]     += f.x;
            acc[2 * t + 1] += f.y;
        }
    }
    const float inv = 1.f / fmaxf((float)deg, 1.f);
    union { __half h[8]; uint4 u; } o;
#pragma unroll
    for (int j = 0; j < 8; j++) o.h[j] = __float2half_rn(acc[j] * inv);
    row[lane] = o.u;                                    // mean half
    row[lane + 32] = xb[(size_t)node * 32 + lane];      // x half: direct copy
}

// ---------------- fp16 mma.sync GEMM: out = A@B^T + bias ----------------
#define BM 128
#define BN 128
#define KC 64
#define NCHUNK (KTOT / KC)                  // 8
#define TILE_BYTES (BM * KC * 2)            // 16384 (128 rows x 128B, SW128)
#define SMEM_TOTAL (4 * TILE_BYTES)         // 65536 -> 2+ CTAs/SM

__device__ __forceinline__ void load_chunk(uint32_t sb, int s, int c, int row0, int col0, int tid) {
    const __half* srcs[2];
    srcs[0] = g_A + (size_t)row0 * KTOT + c * KC;
    srcs[1] = g_B + (size_t)col0 * KTOT + c * KC;
#pragma unroll
    for (int i = 0; i < 8; i++) {
        int lin  = i * 256 + tid;        // 0..2047, 16B granules
        int tile = lin >> 10;
        int w    = lin & 1023;
        int r    = w >> 3;               // row 0..127
        int j    = w & 7;                // 16B col within 128B row
        const char* gp = (const char*)srcs[tile] + (size_t)r * (KTOT * 2) + j * 16;
        uint32_t daddr = sb + (uint32_t)(s * 2 + tile) * TILE_BYTES + sw_off(r, j);
        asm volatile("cp.async.cg.shared.global [%0], [%1], 16;" :: "r"(daddr), "l"(gp) : "memory");
    }
    asm volatile("cp.async.commit_group;" ::: "memory");
}

__global__ __launch_bounds__(256, 2) void gemm_f16(
    const float* __restrict__ bias, float* __restrict__ out)
{
    extern __shared__ char smem[];
    uint32_t sb = smem_u32(smem);
    const int tid = threadIdx.x, wid = tid >> 5, lane = tid & 31;
    const int row0 = blockIdx.y * BM, col0 = blockIdx.x * BN;
    const int warp_m = (wid & 3) * 32;      // 0,32,64,96
    const int warp_n = (wid >> 2) * 64;     // 0,64

    float acc[2][8][4];
#pragma unroll
    for (int mi = 0; mi < 2; mi++)
#pragma unroll
        for (int ni = 0; ni < 8; ni++)
#pragma unroll
            for (int j = 0; j < 4; j++) acc[mi][ni][j] = 0.f;

    const int lmat = lane >> 3;             // matrix 0..3
    const int lrow = lane & 7;              // row within 8x8

    load_chunk(sb, 0, 0, row0, col0, tid);

    for (int c = 0; c < NCHUNK; c++) {
        const int s = c & 1;
        if (c + 1 < NCHUNK) {
            load_chunk(sb, s ^ 1, c + 1, row0, col0, tid);
            asm volatile("cp.async.wait_group 1;" ::: "memory");
        } else {
            asm volatile("cp.async.wait_group 0;" ::: "memory");
        }
        __syncthreads();

        const uint32_t tA = sb + (uint32_t)(s * 2 + 0) * TILE_BYTES;
        const uint32_t tB = sb + (uint32_t)(s * 2 + 1) * TILE_BYTES;

#pragma unroll
        for (int kk = 0; kk < 4; kk++) {    // 4 k16-steps per KC=64
            uint32_t af[2][4];
#pragma unroll
            for (int mi = 0; mi < 2; mi++) {
                int ra = warp_m + mi * 16 + (lmat & 1) * 8 + lrow;
                int ja = kk * 2 + (lmat >> 1);
                ldmatrix_x4(af[mi], tA + sw_off(ra, ja));
            }
            int rb = warp_n + (lmat >> 1) * 8 + lrow;
            int jb = kk * 2 + (lmat & 1);
#pragma unroll
            for (int np = 0; np < 4; np++) {
                uint32_t bf[4];
                ldmatrix_x4(bf, tB + sw_off(rb + np * 16, jb));
#pragma unroll
                for (int mi = 0; mi < 2; mi++) {
#pragma unroll
                    for (int q = 0; q < 2; q++) {
                        mma_f16(acc[mi][np * 2 + q], af[mi], bf[2 * q], bf[2 * q + 1]);
                    }
                }
            }
        }
        __syncthreads();
    }

    const int qrow = lane >> 2, qcol = (lane & 3) * 2;
#pragma unroll
    for (int mi = 0; mi < 2; mi++) {
        int r0 = row0 + warp_m + mi * 16 + qrow;
#pragma unroll
        for (int ni = 0; ni < 8; ni++) {
            int cn = col0 + warp_n + ni * 8 + qcol;
            float2 bb = *(const float2*)(bias + cn);
            if (r0 < N_NODES) {
                float2 o0 = make_float2(acc[mi][ni][0] + bb.x, acc[mi][ni][1] + bb.y);
                *(float2*)(out + (size_t)r0 * D_HID + cn) = o0;
            }
            if (r0 + 8 < N_NODES) {
                float2 o1 = make_float2(acc[mi][ni][2] + bb.x, acc[mi][ni][3] + bb.y);
                *(float2*)(out + (size_t)(r0 + 8) * D_HID + cn) = o1;
            }
        }
    }
}

// ---------------- launch ----------------
extern "C" void kernel_launch(void* const* d_in, const int* in_sizes, int n_in,
                              void* d_out, int out_size) {
    const float* x    = (const float*)d_in[0];
    const void*  eidx = d_in[1];
    const float* Wl   = (const float*)d_in[2];
    const float* Wr   = (const float*)d_in[3];
    const float* bias = (const float*)d_in[4];
    float* out = (float*)d_out;

    cudaFuncSetAttribute(gemm_f16, cudaFuncAttributeMaxDynamicSharedMemorySize, SMEM_TOTAL);

    prep_kernel<<<PREP_BLOCKS, 256>>>(x, Wl, Wr);
    hist_kernel<<<EDGE_BLOCKS, 256>>>(eidx);
    scan_kernel<<<SCAN_BLOCKS, 1024>>>();
    fill_kernel<<<EDGE_BLOCKS, 256>>>(eidx);
    gather_kernel<<<M_PAD / 8, 256>>>();

    dim3 grid(D_HID / BN, M_PAD / BM);      // (cols, rows) — L2 A-reuse
    gemm_f16<<<grid, 256, SMEM_TOTAL>>>(bias, out);
}